// round 5
// baseline (speedup 1.0000x reference)
#include <cuda_runtime.h>
#include <cstdint>
#include <math.h>

// ============================================================================
// BinaryLinear: y[8192,4096] = x[8192,4096] @ (aa*tanh(kk*W))^T + bias
// mma.sync.m16n8k8.tf32 register GEMM.
// CTA 128x256, 8 warps (2x4), warp tile 64x64, 3-stage cp.async, TK=32.
// W pre-rounded to tf32 (RNA); X fed raw fp32 (HMMA truncates -> unbiased-ish).
// Register double-buffered fragments to hide LDS latency under HMMA.
// ============================================================================

#define MDIM 8192
#define NDIM 4096
#define KDIM 4096

#define TM 128
#define TN 256
#define TK 32
#define NSTAGES 3
#define KITERS (KDIM / TK)              // 128

#define A_STAGE_FLOATS (TM * TK)        // 4096
#define B_STAGE_FLOATS (TN * TK)        // 8192
#define STAGE_FLOATS (A_STAGE_FLOATS + B_STAGE_FLOATS)   // 12288 = 48KB
#define SMEM_BYTES (NSTAGES * STAGE_FLOATS * 4)          // 147456

// pre-rounded tf32 W (persistent scratch)
__device__ float g_wb[NDIM * KDIM];

// ---------------------------------------------------------------------------
__device__ __forceinline__ uint32_t smem_u32(const void* p) {
    uint32_t a;
    asm("{ .reg .u64 t; cvta.to.shared.u64 t, %1; cvt.u32.u64 %0, t; }" : "=r"(a) : "l"(p));
    return a;
}

__device__ __forceinline__ void cp_async16(uint32_t smem_dst, const void* gmem_src) {
    asm volatile("cp.async.cg.shared.global [%0], [%1], 16;" :: "r"(smem_dst), "l"(gmem_src));
}
#define CP_COMMIT() asm volatile("cp.async.commit_group;" ::: "memory")
#define CP_WAIT(n)  asm volatile("cp.async.wait_group %0;" :: "n"(n) : "memory")

__device__ __forceinline__ uint32_t f2tf32(float f) {
    uint32_t u;
    asm("cvt.rna.tf32.f32 %0, %1;" : "=r"(u) : "f"(f));
    return u;
}

__device__ __forceinline__ void mma_tf32(float d[4], const uint32_t a[4],
                                         const uint32_t b[2], const float c[4]) {
    asm volatile(
        "mma.sync.aligned.m16n8k8.row.col.f32.tf32.tf32.f32 "
        "{%0,%1,%2,%3}, {%4,%5,%6,%7}, {%8,%9}, {%10,%11,%12,%13};"
        : "=f"(d[0]), "=f"(d[1]), "=f"(d[2]), "=f"(d[3])
        : "r"(a[0]), "r"(a[1]), "r"(a[2]), "r"(a[3]),
          "r"(b[0]), "r"(b[1]),
          "f"(c[0]), "f"(c[1]), "f"(c[2]), "f"(c[3]));
}

// ---------------------------------------------------------------------------
// Prep: wb = round_tf32(aa * tanh(kk * w))
// ---------------------------------------------------------------------------
__global__ void __launch_bounds__(256) prep_w(const float4* __restrict__ w,
                                              const float* __restrict__ kk,
                                              const float* __restrict__ aa) {
    int i = blockIdx.x * 256 + threadIdx.x;
    float k = *kk, a = *aa;
    float4 v = w[i];
    uint4 r;
    r.x = f2tf32(a * tanhf(k * v.x));
    r.y = f2tf32(a * tanhf(k * v.y));
    r.z = f2tf32(a * tanhf(k * v.z));
    r.w = f2tf32(a * tanhf(k * v.w));
    reinterpret_cast<uint4*>(g_wb)[i] = r;
}

// ---------------------------------------------------------------------------
// Load one 32-K stage: A 128x32f (from x) + B 256x32f (from wb), 16B granules,
// XOR swizzle. Element (row,col) -> float index row*32 + (col ^ ((row&7)<<2)).
// ---------------------------------------------------------------------------
__device__ __forceinline__ void load_stage(const float* __restrict__ x,
                                           const float* __restrict__ wb,
                                           int m0, int n0, int k0,
                                           uint32_t sdst, int tid) {
#pragma unroll
    for (int i = 0; i < 4; i++) {                 // A: 1024 granules / 256 thr
        int g = tid + i * 256;
        int row = g >> 3, c = g & 7;
        cp_async16(sdst + row * 128 + ((c ^ (row & 7)) << 4),
                   x + (size_t)(m0 + row) * KDIM + k0 + c * 4);
    }
#pragma unroll
    for (int i = 0; i < 8; i++) {                 // B: 2048 granules
        int g = tid + i * 256;
        int row = g >> 3, c = g & 7;
        cp_async16(sdst + A_STAGE_FLOATS * 4 + row * 128 + ((c ^ (row & 7)) << 4),
                   wb + (size_t)(n0 + row) * KDIM + k0 + c * 4);
    }
}

__device__ __forceinline__ int swz(int row, int col) {
    return row * 32 + (col ^ ((row & 7) << 2));
}

// ---------------------------------------------------------------------------
// GEMM: warp tile 64x64 (4 x 8 of m16n8k8), 4 k-steps/stage, reg double-buffer
// ---------------------------------------------------------------------------
__global__ void __launch_bounds__(256, 1) gemm_kernel(const float* __restrict__ x,
                                                      const float* __restrict__ bias,
                                                      float* __restrict__ out) {
    extern __shared__ float smemf[];
    const uint32_t sbase = smem_u32(smemf);

    const int tid = threadIdx.x;
    const int wid = tid >> 5;
    const int lane = tid & 31;
    const int wm = wid >> 2;          // 0..1 -> 64-row slab
    const int wn = wid & 3;           // 0..3 -> 64-col slab
    const int lr = lane >> 2;         // 0..7
    const int lc = lane & 3;          // 0..3

    // grouped tile swizzle: 64 m-tiles x 16 n-tiles, GROUP_M = 8
    const int pid = blockIdx.x;
    const int group = pid >> 7;                   // / (8*16)
    const int rem = pid & 127;
    const int pm = (group << 3) + (rem & 7);
    const int pn = rem >> 3;
    const int m0 = pm * TM;
    const int n0 = pn * TN;

    float acc[4][8][4];
#pragma unroll
    for (int i = 0; i < 4; i++)
#pragma unroll
        for (int j = 0; j < 8; j++) {
            acc[i][j][0] = 0.f; acc[i][j][1] = 0.f;
            acc[i][j][2] = 0.f; acc[i][j][3] = 0.f;
        }

    // prologue: fill stages 0,1
#pragma unroll
    for (int s = 0; s < NSTAGES - 1; s++) {
        load_stage(x, g_wb, m0, n0, s * TK, sbase + s * STAGE_FLOATS * 4, tid);
        CP_COMMIT();
    }

    uint32_t af[2][4][4];
    uint32_t bf[2][8][2];

    const int ar0 = wm * 64 + lr;     // A frag base row
    const int br0 = wn * 64 + lr;     // B frag base row

    for (int it = 0; it < KITERS; ++it) {
        const int s = it % NSTAGES;
        CP_WAIT(1);              // stage `it` resident (one group per iter)
        __syncthreads();

        const float* aS = smemf + s * STAGE_FLOATS;   // A: 128x32
        const float* bS = aS + A_STAGE_FLOATS;        // B: 256x32

        // frag load for kq = 0 into buffer 0
        {
            const int c0 = lc;
#pragma unroll
            for (int ms = 0; ms < 4; ms++) {
                const int r0 = ar0 + ms * 16;
                af[0][ms][0] = __float_as_uint(aS[swz(r0,     c0)]);
                af[0][ms][1] = __float_as_uint(aS[swz(r0 + 8, c0)]);
                af[0][ms][2] = __float_as_uint(aS[swz(r0,     c0 + 4)]);
                af[0][ms][3] = __float_as_uint(aS[swz(r0 + 8, c0 + 4)]);
            }
#pragma unroll
            for (int ns = 0; ns < 8; ns++) {
                const int nr = br0 + ns * 8;
                bf[0][ns][0] = __float_as_uint(bS[swz(nr, c0)]);
                bf[0][ns][1] = __float_as_uint(bS[swz(nr, c0 + 4)]);
            }
        }

        // issue next-stage gmem prefetch early (max latency slack)
        const int jt = it + NSTAGES - 1;
        if (jt < KITERS)
            load_stage(x, g_wb, m0, n0, jt * TK,
                       sbase + (jt % NSTAGES) * STAGE_FLOATS * 4, tid);
        CP_COMMIT();                              // always commit: CP_WAIT(1) stays valid

#pragma unroll
        for (int kq = 0; kq < 4; kq++) {
            const int cur = kq & 1, nxt = cur ^ 1;
            if (kq < 3) {                         // prefetch kq+1 frags
                const int c1 = (kq + 1) * 8 + lc;
#pragma unroll
                for (int ms = 0; ms < 4; ms++) {
                    const int r0 = ar0 + ms * 16;
                    af[nxt][ms][0] = __float_as_uint(aS[swz(r0,     c1)]);
                    af[nxt][ms][1] = __float_as_uint(aS[swz(r0 + 8, c1)]);
                    af[nxt][ms][2] = __float_as_uint(aS[swz(r0,     c1 + 4)]);
                    af[nxt][ms][3] = __float_as_uint(aS[swz(r0 + 8, c1 + 4)]);
                }
#pragma unroll
                for (int ns = 0; ns < 8; ns++) {
                    const int nr = br0 + ns * 8;
                    bf[nxt][ns][0] = __float_as_uint(bS[swz(nr, c1)]);
                    bf[nxt][ns][1] = __float_as_uint(bS[swz(nr, c1 + 4)]);
                }
            }
#pragma unroll
            for (int ms = 0; ms < 4; ms++)
#pragma unroll
                for (int ns = 0; ns < 8; ns++)
                    mma_tf32(acc[ms][ns], af[cur][ms], bf[cur][ns], acc[ms][ns]);
        }
    }

    // epilogue: c0,c1 at (row, 2*lc), c2,c3 at (row+8, 2*lc)
#pragma unroll
    for (int ms = 0; ms < 4; ms++) {
        const int rg = m0 + wm * 64 + ms * 16 + lr;
        float* o0 = out + (size_t)rg * NDIM;
        float* o1 = out + (size_t)(rg + 8) * NDIM;
#pragma unroll
        for (int ns = 0; ns < 8; ns++) {
            const int cg = n0 + wn * 64 + ns * 8 + 2 * lc;
            const float2 bv = *reinterpret_cast<const float2*>(bias + cg);
            float2 v0, v1;
            v0.x = acc[ms][ns][0] + bv.x;  v0.y = acc[ms][ns][1] + bv.y;
            v1.x = acc[ms][ns][2] + bv.x;  v1.y = acc[ms][ns][3] + bv.y;
            *reinterpret_cast<float2*>(o0 + cg) = v0;
            *reinterpret_cast<float2*>(o1 + cg) = v1;
        }
    }
}

// ---------------------------------------------------------------------------
extern "C" void kernel_launch(void* const* d_in, const int* in_sizes, int n_in,
                              void* d_out, int out_size) {
    const float* x = (const float*)d_in[0];      // [4,2048,4096]
    const float* w = (const float*)d_in[1];      // [4096,4096]
    const float* bias = (const float*)d_in[2];   // [4096]
    const float* kk = (const float*)d_in[3];
    const float* aa = (const float*)d_in[4];
    float* out = (float*)d_out;                  // [4,2048,4096]

    prep_w<<<NDIM * KDIM / 1024, 256>>>((const float4*)w, kk, aa);

    cudaFuncSetAttribute(gemm_kernel, cudaFuncAttributeMaxDynamicSharedMemorySize, SMEM_BYTES);
    gemm_kernel<<<(MDIM / TM) * (NDIM / TN), 256, SMEM_BYTES>>>(x, bias, out);
}

// round 6
// speedup vs baseline: 1.0192x; 1.0192x over previous
#include <cuda_runtime.h>
#include <cstdint>
#include <math.h>

// ============================================================================
// BinaryLinear: y[8192,4096] = x[8192,4096] @ (aa*tanh(kk*W))^T + bias
// mma.sync.m16n8k8.tf32 register GEMM.
// CTA 128x128, 4 warps (2x2), warp tile 64x64, 3-stage cp.async, TK=32.
// 2 CTAs/SM -> unaligned barriers keep the tensor pipe fed during LDS phases.
// W pre-rounded to tf32 (RNA); X fed raw fp32 (HW truncation, rel_err ~4.6e-4).
// ============================================================================

#define MDIM 8192
#define NDIM 4096
#define KDIM 4096

#define TM 128
#define TN 128
#define TK 32
#define NSTAGES 3
#define KITERS (KDIM / TK)              // 128

#define A_STAGE_FLOATS (TM * TK)        // 4096
#define B_STAGE_FLOATS (TN * TK)        // 4096
#define STAGE_FLOATS (A_STAGE_FLOATS + B_STAGE_FLOATS)   // 8192 = 32KB
#define SMEM_BYTES (NSTAGES * STAGE_FLOATS * 4)          // 98304

// pre-rounded tf32 W (persistent scratch)
__device__ float g_wb[NDIM * KDIM];

// ---------------------------------------------------------------------------
__device__ __forceinline__ uint32_t smem_u32(const void* p) {
    uint32_t a;
    asm("{ .reg .u64 t; cvta.to.shared.u64 t, %1; cvt.u32.u64 %0, t; }" : "=r"(a) : "l"(p));
    return a;
}

__device__ __forceinline__ void cp_async16(uint32_t smem_dst, const void* gmem_src) {
    asm volatile("cp.async.cg.shared.global [%0], [%1], 16;" :: "r"(smem_dst), "l"(gmem_src));
}
#define CP_COMMIT() asm volatile("cp.async.commit_group;" ::: "memory")
#define CP_WAIT(n)  asm volatile("cp.async.wait_group %0;" :: "n"(n) : "memory")

__device__ __forceinline__ uint32_t f2tf32(float f) {
    uint32_t u;
    asm("cvt.rna.tf32.f32 %0, %1;" : "=r"(u) : "f"(f));
    return u;
}

__device__ __forceinline__ void mma_tf32(float d[4], const uint32_t a[4],
                                         const uint32_t b[2], const float c[4]) {
    asm volatile(
        "mma.sync.aligned.m16n8k8.row.col.f32.tf32.tf32.f32 "
        "{%0,%1,%2,%3}, {%4,%5,%6,%7}, {%8,%9}, {%10,%11,%12,%13};"
        : "=f"(d[0]), "=f"(d[1]), "=f"(d[2]), "=f"(d[3])
        : "r"(a[0]), "r"(a[1]), "r"(a[2]), "r"(a[3]),
          "r"(b[0]), "r"(b[1]),
          "f"(c[0]), "f"(c[1]), "f"(c[2]), "f"(c[3]));
}

// ---------------------------------------------------------------------------
// Prep: wb = round_tf32(aa * tanh(kk * w))
// ---------------------------------------------------------------------------
__global__ void __launch_bounds__(256) prep_w(const float4* __restrict__ w,
                                              const float* __restrict__ kk,
                                              const float* __restrict__ aa) {
    int i = blockIdx.x * 256 + threadIdx.x;
    float k = *kk, a = *aa;
    float4 v = w[i];
    uint4 r;
    r.x = f2tf32(a * tanhf(k * v.x));
    r.y = f2tf32(a * tanhf(k * v.y));
    r.z = f2tf32(a * tanhf(k * v.z));
    r.w = f2tf32(a * tanhf(k * v.w));
    reinterpret_cast<uint4*>(g_wb)[i] = r;
}

// ---------------------------------------------------------------------------
// Load one 32-K stage: A 128x32f (from x) + B 128x32f (from wb), 16B granules,
// XOR swizzle. Element (row,col) -> float index row*32 + (col ^ ((row&7)<<2)).
// 128 threads: 8 granule-batches each for A and B.
// ---------------------------------------------------------------------------
__device__ __forceinline__ void load_stage(const float* __restrict__ x,
                                           const float* __restrict__ wb,
                                           int m0, int n0, int k0,
                                           uint32_t sdst, int tid) {
#pragma unroll
    for (int i = 0; i < 8; i++) {                 // A: 1024 granules / 128 thr
        int g = tid + i * 128;
        int row = g >> 3, c = g & 7;
        cp_async16(sdst + row * 128 + ((c ^ (row & 7)) << 4),
                   x + (size_t)(m0 + row) * KDIM + k0 + c * 4);
    }
#pragma unroll
    for (int i = 0; i < 8; i++) {                 // B: 1024 granules
        int g = tid + i * 128;
        int row = g >> 3, c = g & 7;
        cp_async16(sdst + A_STAGE_FLOATS * 4 + row * 128 + ((c ^ (row & 7)) << 4),
                   wb + (size_t)(n0 + row) * KDIM + k0 + c * 4);
    }
}

__device__ __forceinline__ int swz(int row, int col) {
    return row * 32 + (col ^ ((row & 7) << 2));
}

// ---------------------------------------------------------------------------
// GEMM: 4 warps (2x2), warp tile 64x64 (4 x 8 of m16n8k8), 4 k-steps/stage
// ---------------------------------------------------------------------------
__global__ void __launch_bounds__(128, 2) gemm_kernel(const float* __restrict__ x,
                                                      const float* __restrict__ bias,
                                                      float* __restrict__ out) {
    extern __shared__ float smemf[];
    const uint32_t sbase = smem_u32(smemf);

    const int tid = threadIdx.x;
    const int wid = tid >> 5;
    const int lane = tid & 31;
    const int wm = wid >> 1;          // 0..1 -> 64-row slab
    const int wn = wid & 1;           // 0..1 -> 64-col slab
    const int lr = lane >> 2;         // 0..7
    const int lc = lane & 3;          // 0..3

    // grouped tile swizzle: 64 m-tiles x 32 n-tiles, GROUP_M = 8
    const int pid = blockIdx.x;
    const int group = pid >> 8;                   // / (8*32)
    const int rem = pid & 255;
    const int pm = (group << 3) + (rem & 7);
    const int pn = rem >> 3;
    const int m0 = pm * TM;
    const int n0 = pn * TN;

    float acc[4][8][4];
#pragma unroll
    for (int i = 0; i < 4; i++)
#pragma unroll
        for (int j = 0; j < 8; j++) {
            acc[i][j][0] = 0.f; acc[i][j][1] = 0.f;
            acc[i][j][2] = 0.f; acc[i][j][3] = 0.f;
        }

    // prologue: fill stages 0,1
#pragma unroll
    for (int s = 0; s < NSTAGES - 1; s++) {
        load_stage(x, g_wb, m0, n0, s * TK, sbase + s * STAGE_FLOATS * 4, tid);
        CP_COMMIT();
    }

    const int ar0 = wm * 64 + lr;     // A frag base row
    const int br0 = wn * 64 + lr;     // B frag base row

    for (int it = 0; it < KITERS; ++it) {
        const int s = it % NSTAGES;
        CP_WAIT(1);              // stage `it` resident (one group per iter)
        __syncthreads();

        const float* aS = smemf + s * STAGE_FLOATS;   // A: 128x32
        const float* bS = aS + A_STAGE_FLOATS;        // B: 128x32

        // issue next-stage gmem prefetch early (max latency slack)
        const int jt = it + NSTAGES - 1;
        if (jt < KITERS)
            load_stage(x, g_wb, m0, n0, jt * TK,
                       sbase + (jt % NSTAGES) * STAGE_FLOATS * 4, tid);
        CP_COMMIT();                              // always commit: CP_WAIT(1) stays valid

#pragma unroll
        for (int kq = 0; kq < 4; kq++) {
            const int c0 = kq * 8 + lc;
            uint32_t af[4][4];
#pragma unroll
            for (int ms = 0; ms < 4; ms++) {
                const int r0 = ar0 + ms * 16;
                af[ms][0] = __float_as_uint(aS[swz(r0,     c0)]);
                af[ms][1] = __float_as_uint(aS[swz(r0 + 8, c0)]);
                af[ms][2] = __float_as_uint(aS[swz(r0,     c0 + 4)]);
                af[ms][3] = __float_as_uint(aS[swz(r0 + 8, c0 + 4)]);
            }
            uint32_t bf[8][2];
#pragma unroll
            for (int ns = 0; ns < 8; ns++) {
                const int nr = br0 + ns * 8;
                bf[ns][0] = __float_as_uint(bS[swz(nr, c0)]);
                bf[ns][1] = __float_as_uint(bS[swz(nr, c0 + 4)]);
            }
#pragma unroll
            for (int ms = 0; ms < 4; ms++)
#pragma unroll
                for (int ns = 0; ns < 8; ns++)
                    mma_tf32(acc[ms][ns], af[ms], bf[ns], acc[ms][ns]);
        }
    }

    // epilogue: c0,c1 at (row, 2*lc), c2,c3 at (row+8, 2*lc)
#pragma unroll
    for (int ms = 0; ms < 4; ms++) {
        const int rg = m0 + wm * 64 + ms * 16 + lr;
        float* o0 = out + (size_t)rg * NDIM;
        float* o1 = out + (size_t)(rg + 8) * NDIM;
#pragma unroll
        for (int ns = 0; ns < 8; ns++) {
            const int cg = n0 + wn * 64 + ns * 8 + 2 * lc;
            const float2 bv = *reinterpret_cast<const float2*>(bias + cg);
            float2 v0, v1;
            v0.x = acc[ms][ns][0] + bv.x;  v0.y = acc[ms][ns][1] + bv.y;
            v1.x = acc[ms][ns][2] + bv.x;  v1.y = acc[ms][ns][3] + bv.y;
            *reinterpret_cast<float2*>(o0 + cg) = v0;
            *reinterpret_cast<float2*>(o1 + cg) = v1;
        }
    }
}

// ---------------------------------------------------------------------------
extern "C" void kernel_launch(void* const* d_in, const int* in_sizes, int n_in,
                              void* d_out, int out_size) {
    const float* x = (const float*)d_in[0];      // [4,2048,4096]
    const float* w = (const float*)d_in[1];      // [4096,4096]
    const float* bias = (const float*)d_in[2];   // [4096]
    const float* kk = (const float*)d_in[3];
    const float* aa = (const float*)d_in[4];
    float* out = (float*)d_out;                  // [4,2048,4096]

    prep_w<<<NDIM * KDIM / 1024, 256>>>((const float4*)w, kk, aa);

    cudaFuncSetAttribute(gemm_kernel, cudaFuncAttributeMaxDynamicSharedMemorySize, SMEM_BYTES);
    gemm_kernel<<<(MDIM / TM) * (NDIM / TN), 128, SMEM_BYTES>>>(x, bias, out);
}

// round 7
// speedup vs baseline: 2.0140x; 1.9760x over previous
#include <cuda_runtime.h>
#include <cuda_fp16.h>
#include <cstdint>
#include <math.h>

// ============================================================================
// BinaryLinear: y[8192,4096] = x[8192,4096] @ (aa*tanh(kk*W))^T + bias
// fp16 mma.sync.m16n8k16 register GEMM (fp32 accumulate).
// CTA 128x128, 4 warps (2x2), warp tile 64x64, 4-stage cp.async, TK=32 halves.
// Both operands pre-converted to fp16 RN (same 11-bit mantissa as tf32).
// ============================================================================

#define MDIM 8192
#define NDIM 4096
#define KDIM 4096

#define TM 128
#define TN 128
#define TK 32                          // halves per stage-row (64B)
#define NSTAGES 4
#define KITERS (KDIM / TK)             // 128

#define A_STAGE_BYTES (TM * TK * 2)    // 8192
#define B_STAGE_BYTES (TN * TK * 2)    // 8192
#define STAGE_BYTES (A_STAGE_BYTES + B_STAGE_BYTES)     // 16384
#define SMEM_BYTES (NSTAGES * STAGE_BYTES)              // 65536

// fp16 operands (persistent scratch)
__device__ __half g_wh[NDIM * KDIM];   // fp16(aa*tanh(kk*W))
__device__ __half g_xh[MDIM * KDIM];   // fp16(x)

// ---------------------------------------------------------------------------
__device__ __forceinline__ uint32_t smem_u32(const void* p) {
    uint32_t a;
    asm("{ .reg .u64 t; cvta.to.shared.u64 t, %1; cvt.u32.u64 %0, t; }" : "=r"(a) : "l"(p));
    return a;
}

__device__ __forceinline__ void cp_async16(uint32_t smem_dst, const void* gmem_src) {
    asm volatile("cp.async.cg.shared.global [%0], [%1], 16;" :: "r"(smem_dst), "l"(gmem_src));
}
#define CP_COMMIT() asm volatile("cp.async.commit_group;" ::: "memory")
#define CP_WAIT(n)  asm volatile("cp.async.wait_group %0;" :: "n"(n) : "memory")

__device__ __forceinline__ void mma_f16(float d[4], const uint32_t a[4],
                                        const uint32_t b[2], const float c[4]) {
    asm volatile(
        "mma.sync.aligned.m16n8k16.row.col.f32.f16.f16.f32 "
        "{%0,%1,%2,%3}, {%4,%5,%6,%7}, {%8,%9}, {%10,%11,%12,%13};"
        : "=f"(d[0]), "=f"(d[1]), "=f"(d[2]), "=f"(d[3])
        : "r"(a[0]), "r"(a[1]), "r"(a[2]), "r"(a[3]),
          "r"(b[0]), "r"(b[1]),
          "f"(c[0]), "f"(c[1]), "f"(c[2]), "f"(c[3]));
}

// ---------------------------------------------------------------------------
// Prep: 8 floats -> 8 halves per thread (16B store)
// ---------------------------------------------------------------------------
__global__ void __launch_bounds__(256) prep_w(const float4* __restrict__ w,
                                              const float* __restrict__ kk,
                                              const float* __restrict__ aa) {
    int i = blockIdx.x * 256 + threadIdx.x;
    float k = *kk, a = *aa;
    float4 v0 = w[2 * i], v1 = w[2 * i + 1];
    __half2 h0 = __floats2half2_rn(a * tanhf(k * v0.x), a * tanhf(k * v0.y));
    __half2 h1 = __floats2half2_rn(a * tanhf(k * v0.z), a * tanhf(k * v0.w));
    __half2 h2 = __floats2half2_rn(a * tanhf(k * v1.x), a * tanhf(k * v1.y));
    __half2 h3 = __floats2half2_rn(a * tanhf(k * v1.z), a * tanhf(k * v1.w));
    uint4 o;
    o.x = *reinterpret_cast<uint32_t*>(&h0);
    o.y = *reinterpret_cast<uint32_t*>(&h1);
    o.z = *reinterpret_cast<uint32_t*>(&h2);
    o.w = *reinterpret_cast<uint32_t*>(&h3);
    reinterpret_cast<uint4*>(g_wh)[i] = o;
}

__global__ void __launch_bounds__(256) prep_x(const float4* __restrict__ x) {
    int i = blockIdx.x * 256 + threadIdx.x;
    float4 v0 = x[2 * i], v1 = x[2 * i + 1];
    __half2 h0 = __floats2half2_rn(v0.x, v0.y);
    __half2 h1 = __floats2half2_rn(v0.z, v0.w);
    __half2 h2 = __floats2half2_rn(v1.x, v1.y);
    __half2 h3 = __floats2half2_rn(v1.z, v1.w);
    uint4 o;
    o.x = *reinterpret_cast<uint32_t*>(&h0);
    o.y = *reinterpret_cast<uint32_t*>(&h1);
    o.z = *reinterpret_cast<uint32_t*>(&h2);
    o.w = *reinterpret_cast<uint32_t*>(&h3);
    reinterpret_cast<uint4*>(g_xh)[i] = o;
}

// ---------------------------------------------------------------------------
// SMEM layout: rows of 32 halves (64B = 4 x 16B granules).
// Granule c of row r stored at slot c ^ ((r>>1)&3)  (16B units).
// Word (4B) wc of row r at word index r*16 + (wc ^ (((r>>1)&3)<<2)).
// Conflict-free for frag loads: even rows span banks 0-15, odd rows 16-31.
// ---------------------------------------------------------------------------
__device__ __forceinline__ int swzw(int row, int wc) {
    return row * 16 + (wc ^ (((row >> 1) & 3) << 2));
}

// Load one 32-K stage: A 128x32h (from xh) + B 128x32h (from wh).
// 1024 granules / 128 threads = 8 cp.async per thread.
__device__ __forceinline__ void load_stage(const __half* __restrict__ xh,
                                           const __half* __restrict__ wh,
                                           int m0, int n0, int k0,
                                           uint32_t sdst, int tid) {
#pragma unroll
    for (int i = 0; i < 4; i++) {                 // A: 512 granules
        int g = tid + i * 128;
        int row = g >> 2, c = g & 3;
        cp_async16(sdst + row * 64 + ((c ^ ((row >> 1) & 3)) << 4),
                   xh + (size_t)(m0 + row) * KDIM + k0 + c * 8);
    }
#pragma unroll
    for (int i = 0; i < 4; i++) {                 // B: 512 granules
        int g = tid + i * 128;
        int row = g >> 2, c = g & 3;
        cp_async16(sdst + A_STAGE_BYTES + row * 64 + ((c ^ ((row >> 1) & 3)) << 4),
                   wh + (size_t)(n0 + row) * KDIM + k0 + c * 8);
    }
}

// ---------------------------------------------------------------------------
// GEMM: 4 warps (2x2), warp tile 64x64 (4 x 8 of m16n8k16), 2 k-steps/stage
// ---------------------------------------------------------------------------
__global__ void __launch_bounds__(128, 2) gemm_kernel(const float* __restrict__ bias,
                                                      float* __restrict__ out) {
    extern __shared__ char smem_raw[];
    const uint32_t sbase = smem_u32(smem_raw);

    const int tid = threadIdx.x;
    const int wid = tid >> 5;
    const int lane = tid & 31;
    const int wm = wid >> 1;          // 0..1 -> 64-row slab
    const int wn = wid & 1;           // 0..1 -> 64-col slab
    const int lr = lane >> 2;         // 0..7
    const int lc = lane & 3;          // 0..3

    // grouped tile swizzle: 64 m-tiles x 32 n-tiles, GROUP_M = 8
    const int pid = blockIdx.x;
    const int group = pid >> 8;                   // / (8*32)
    const int rem = pid & 255;
    const int pm = (group << 3) + (rem & 7);
    const int pn = rem >> 3;
    const int m0 = pm * TM;
    const int n0 = pn * TN;

    float acc[4][8][4];
#pragma unroll
    for (int i = 0; i < 4; i++)
#pragma unroll
        for (int j = 0; j < 8; j++) {
            acc[i][j][0] = 0.f; acc[i][j][1] = 0.f;
            acc[i][j][2] = 0.f; acc[i][j][3] = 0.f;
        }

    // prologue: fill stages 0..2
#pragma unroll
    for (int s = 0; s < NSTAGES - 1; s++) {
        load_stage(g_xh, g_wh, m0, n0, s * TK, sbase + s * STAGE_BYTES, tid);
        CP_COMMIT();
    }

    const int ar0 = wm * 64 + lr;     // A frag base row
    const int br0 = wn * 64 + lr;     // B frag base row

    for (int it = 0; it < KITERS; ++it) {
        const int s = it & (NSTAGES - 1);
        CP_WAIT(2);              // stage `it` resident (one group per iter)
        __syncthreads();

        const uint32_t* aW = reinterpret_cast<const uint32_t*>(smem_raw + s * STAGE_BYTES);
        const uint32_t* bW = aW + A_STAGE_BYTES / 4;

        // issue next-stage gmem prefetch early
        const int jt = it + NSTAGES - 1;
        if (jt < KITERS)
            load_stage(g_xh, g_wh, m0, n0, jt * TK,
                       sbase + (jt & (NSTAGES - 1)) * STAGE_BYTES, tid);
        CP_COMMIT();                              // always commit: CP_WAIT(2) stays valid

#pragma unroll
        for (int kq = 0; kq < 2; kq++) {          // 2 x k16 steps
            const int w0 = kq * 8 + lc;
            uint32_t af[4][4];
#pragma unroll
            for (int ms = 0; ms < 4; ms++) {
                const int r0 = ar0 + ms * 16;
                af[ms][0] = aW[swzw(r0,     w0)];
                af[ms][1] = aW[swzw(r0 + 8, w0)];
                af[ms][2] = aW[swzw(r0,     w0 + 4)];
                af[ms][3] = aW[swzw(r0 + 8, w0 + 4)];
            }
            uint32_t bf[8][2];
#pragma unroll
            for (int ns = 0; ns < 8; ns++) {
                const int nr = br0 + ns * 8;
                bf[ns][0] = bW[swzw(nr, w0)];
                bf[ns][1] = bW[swzw(nr, w0 + 4)];
            }
#pragma unroll
            for (int ms = 0; ms < 4; ms++)
#pragma unroll
                for (int ns = 0; ns < 8; ns++)
                    mma_f16(acc[ms][ns], af[ms], bf[ns], acc[ms][ns]);
        }
    }

    // epilogue: c0,c1 at (row, 2*lc), c2,c3 at (row+8, 2*lc)
#pragma unroll
    for (int ms = 0; ms < 4; ms++) {
        const int rg = m0 + wm * 64 + ms * 16 + lr;
        float* o0 = out + (size_t)rg * NDIM;
        float* o1 = out + (size_t)(rg + 8) * NDIM;
#pragma unroll
        for (int ns = 0; ns < 8; ns++) {
            const int cg = n0 + wn * 64 + ns * 8 + 2 * lc;
            const float2 bv = *reinterpret_cast<const float2*>(bias + cg);
            float2 v0, v1;
            v0.x = acc[ms][ns][0] + bv.x;  v0.y = acc[ms][ns][1] + bv.y;
            v1.x = acc[ms][ns][2] + bv.x;  v1.y = acc[ms][ns][3] + bv.y;
            *reinterpret_cast<float2*>(o0 + cg) = v0;
            *reinterpret_cast<float2*>(o1 + cg) = v1;
        }
    }
}

// ---------------------------------------------------------------------------
extern "C" void kernel_launch(void* const* d_in, const int* in_sizes, int n_in,
                              void* d_out, int out_size) {
    const float* x = (const float*)d_in[0];      // [4,2048,4096]
    const float* w = (const float*)d_in[1];      // [4096,4096]
    const float* bias = (const float*)d_in[2];   // [4096]
    const float* kk = (const float*)d_in[3];
    const float* aa = (const float*)d_in[4];
    float* out = (float*)d_out;                  // [4,2048,4096]

    prep_w<<<NDIM * KDIM / 2048, 256>>>((const float4*)w, kk, aa);
    prep_x<<<MDIM * KDIM / 2048, 256>>>((const float4*)x);

    cudaFuncSetAttribute(gemm_kernel, cudaFuncAttributeMaxDynamicSharedMemorySize, SMEM_BYTES);
    gemm_kernel<<<(MDIM / TM) * (NDIM / TN), 128, SMEM_BYTES>>>(bias, out);
}

// round 8
// speedup vs baseline: 2.4315x; 1.2073x over previous
#include <cuda_runtime.h>
#include <cuda_fp16.h>
#include <cstdint>
#include <math.h>

// ============================================================================
// BinaryLinear: y[8192,4096] = x[8192,4096] @ (aa*tanh(kk*W))^T + bias
// fp16 mma.sync.m16n8k16 register GEMM (fp32 accumulate), ldmatrix.x4 frags.
// CTA 128x128, 4 warps (2x2), warp tile 64x64, 3-stage cp.async, TK=64 halves.
// 2 CTAs/SM; SW128 swizzle (128B rows).
// ============================================================================

#define MDIM 8192
#define NDIM 4096
#define KDIM 4096

#define TM 128
#define TN 128
#define TK 64                          // halves per stage-row (128B)
#define NSTAGES 3
#define KITERS (KDIM / TK)             // 64

#define A_STAGE_BYTES (TM * TK * 2)    // 16384
#define B_STAGE_BYTES (TN * TK * 2)    // 16384
#define STAGE_BYTES (A_STAGE_BYTES + B_STAGE_BYTES)     // 32768
#define SMEM_BYTES (NSTAGES * STAGE_BYTES)              // 98304

// fp16 operands (persistent scratch)
__device__ __half g_wh[NDIM * KDIM];   // fp16(aa*tanh(kk*W))
__device__ __half g_xh[MDIM * KDIM];   // fp16(x)

// ---------------------------------------------------------------------------
__device__ __forceinline__ uint32_t smem_u32(const void* p) {
    uint32_t a;
    asm("{ .reg .u64 t; cvta.to.shared.u64 t, %1; cvt.u32.u64 %0, t; }" : "=r"(a) : "l"(p));
    return a;
}

__device__ __forceinline__ void cp_async16(uint32_t smem_dst, const void* gmem_src) {
    asm volatile("cp.async.cg.shared.global [%0], [%1], 16;" :: "r"(smem_dst), "l"(gmem_src));
}
#define CP_COMMIT() asm volatile("cp.async.commit_group;" ::: "memory")
#define CP_WAIT(n)  asm volatile("cp.async.wait_group %0;" :: "n"(n) : "memory")

__device__ __forceinline__ void ldmatrix_x4(uint32_t& r0, uint32_t& r1,
                                            uint32_t& r2, uint32_t& r3, uint32_t addr) {
    asm volatile("ldmatrix.sync.aligned.m8n8.x4.shared.b16 {%0,%1,%2,%3}, [%4];"
                 : "=r"(r0), "=r"(r1), "=r"(r2), "=r"(r3) : "r"(addr));
}

__device__ __forceinline__ void mma_f16(float d[4], const uint32_t a[4],
                                        const uint32_t b[2], const float c[4]) {
    asm volatile(
        "mma.sync.aligned.m16n8k16.row.col.f32.f16.f16.f32 "
        "{%0,%1,%2,%3}, {%4,%5,%6,%7}, {%8,%9}, {%10,%11,%12,%13};"
        : "=f"(d[0]), "=f"(d[1]), "=f"(d[2]), "=f"(d[3])
        : "r"(a[0]), "r"(a[1]), "r"(a[2]), "r"(a[3]),
          "r"(b[0]), "r"(b[1]),
          "f"(c[0]), "f"(c[1]), "f"(c[2]), "f"(c[3]));
}

// ---------------------------------------------------------------------------
// Prep: 8 floats -> 8 halves per thread (16B store)
// ---------------------------------------------------------------------------
__global__ void __launch_bounds__(256) prep_w(const float4* __restrict__ w,
                                              const float* __restrict__ kk,
                                              const float* __restrict__ aa) {
    int i = blockIdx.x * 256 + threadIdx.x;
    float k = *kk, a = *aa;
    float4 v0 = w[2 * i], v1 = w[2 * i + 1];
    __half2 h0 = __floats2half2_rn(a * tanhf(k * v0.x), a * tanhf(k * v0.y));
    __half2 h1 = __floats2half2_rn(a * tanhf(k * v0.z), a * tanhf(k * v0.w));
    __half2 h2 = __floats2half2_rn(a * tanhf(k * v1.x), a * tanhf(k * v1.y));
    __half2 h3 = __floats2half2_rn(a * tanhf(k * v1.z), a * tanhf(k * v1.w));
    uint4 o;
    o.x = *reinterpret_cast<uint32_t*>(&h0);
    o.y = *reinterpret_cast<uint32_t*>(&h1);
    o.z = *reinterpret_cast<uint32_t*>(&h2);
    o.w = *reinterpret_cast<uint32_t*>(&h3);
    reinterpret_cast<uint4*>(g_wh)[i] = o;
}

__global__ void __launch_bounds__(256) prep_x(const float4* __restrict__ x) {
    int i = blockIdx.x * 256 + threadIdx.x;
    float4 v0 = x[2 * i], v1 = x[2 * i + 1];
    __half2 h0 = __floats2half2_rn(v0.x, v0.y);
    __half2 h1 = __floats2half2_rn(v0.z, v0.w);
    __half2 h2 = __floats2half2_rn(v1.x, v1.y);
    __half2 h3 = __floats2half2_rn(v1.z, v1.w);
    uint4 o;
    o.x = *reinterpret_cast<uint32_t*>(&h0);
    o.y = *reinterpret_cast<uint32_t*>(&h1);
    o.z = *reinterpret_cast<uint32_t*>(&h2);
    o.w = *reinterpret_cast<uint32_t*>(&h3);
    reinterpret_cast<uint4*>(g_xh)[i] = o;
}

// ---------------------------------------------------------------------------
// SMEM: rows of 64 halves (128B = 8 x 16B granules), SW128 swizzle:
// granule c of row r stored at slot (c ^ (r&7)).
// ---------------------------------------------------------------------------
// Load one 64-K stage: A 128x64h + B 128x64h. 2048 granules / 128 thr = 16 ea.
__device__ __forceinline__ void load_stage(const __half* __restrict__ xh,
                                           const __half* __restrict__ wh,
                                           int m0, int n0, int k0,
                                           uint32_t sdst, int tid) {
#pragma unroll
    for (int i = 0; i < 8; i++) {                 // A: 1024 granules
        int g = tid + i * 128;
        int row = g >> 3, c = g & 7;
        cp_async16(sdst + row * 128 + ((c ^ (row & 7)) << 4),
                   xh + (size_t)(m0 + row) * KDIM + k0 + c * 8);
    }
#pragma unroll
    for (int i = 0; i < 8; i++) {                 // B: 1024 granules
        int g = tid + i * 128;
        int row = g >> 3, c = g & 7;
        cp_async16(sdst + A_STAGE_BYTES + row * 128 + ((c ^ (row & 7)) << 4),
                   wh + (size_t)(n0 + row) * KDIM + k0 + c * 8);
    }
}

// ---------------------------------------------------------------------------
// GEMM: 4 warps (2x2), warp tile 64x64 (4 x 8 of m16n8k16), 4 k16-steps/stage
// ---------------------------------------------------------------------------
__global__ void __launch_bounds__(128, 2) gemm_kernel(const float* __restrict__ bias,
                                                      float* __restrict__ out) {
    extern __shared__ char smem_raw[];
    const uint32_t sbase = smem_u32(smem_raw);

    const int tid = threadIdx.x;
    const int wid = tid >> 5;
    const int lane = tid & 31;
    const int wm = wid >> 1;          // 0..1 -> 64-row slab
    const int wn = wid & 1;           // 0..1 -> 64-col slab
    const int lr = lane >> 2;         // 0..7
    const int lc = lane & 3;          // 0..3

    // ldmatrix lane decomposition
    const int i8 = lane & 7;          // row within 8x8 matrix
    const int sel = lane >> 3;        // which matrix (0..3)
    // A x4: mat0=(rows+0,g+0) mat1=(rows+8,g+0) mat2=(rows+0,g+1) mat3=(rows+8,g+1)
    const int a_msel = (sel & 1) << 3;
    const int a_gsel = sel >> 1;
    // B x4: mat0=(ns rows,g+0) mat1=(ns rows,g+1) mat2=(ns+1 rows,g+0) mat3=(ns+1,g+1)
    const int b_nsel = (sel >> 1) << 3;
    const int b_gsel = sel & 1;

    // per-lane row-offset bytes (row stride 128B)
    const uint32_t aRowOff = (uint32_t)(wm * 64 + a_msel + i8) * 128;
    const uint32_t bRowOff = (uint32_t)(wn * 64 + b_nsel + i8) * 128;

    // grouped tile swizzle: 64 m-tiles x 32 n-tiles, GROUP_M = 8
    const int pid = blockIdx.x;
    const int group = pid >> 8;                   // / (8*32)
    const int rem = pid & 255;
    const int pm = (group << 3) + (rem & 7);
    const int pn = rem >> 3;
    const int m0 = pm * TM;
    const int n0 = pn * TN;

    float acc[4][8][4];
#pragma unroll
    for (int i = 0; i < 4; i++)
#pragma unroll
        for (int j = 0; j < 8; j++) {
            acc[i][j][0] = 0.f; acc[i][j][1] = 0.f;
            acc[i][j][2] = 0.f; acc[i][j][3] = 0.f;
        }

    // prologue: fill stages 0,1
#pragma unroll
    for (int s = 0; s < NSTAGES - 1; s++) {
        load_stage(g_xh, g_wh, m0, n0, s * TK, sbase + s * STAGE_BYTES, tid);
        CP_COMMIT();
    }

    for (int it = 0; it < KITERS; ++it) {
        const int s = it % NSTAGES;
        CP_WAIT(1);              // stage `it` resident (one group per iter)
        __syncthreads();

        const uint32_t aBase = sbase + s * STAGE_BYTES;
        const uint32_t bBase = aBase + A_STAGE_BYTES;

        // issue next-stage gmem prefetch early
        const int jt = it + NSTAGES - 1;
        if (jt < KITERS)
            load_stage(g_xh, g_wh, m0, n0, jt * TK,
                       sbase + (jt % NSTAGES) * STAGE_BYTES, tid);
        CP_COMMIT();                              // always commit: CP_WAIT(1) stays valid

#pragma unroll
        for (int kq = 0; kq < 4; kq++) {          // 4 x k16 steps
            uint32_t af[4][4];
#pragma unroll
            for (int ms = 0; ms < 4; ms++) {
                const int g = 2 * kq + a_gsel;
                ldmatrix_x4(af[ms][0], af[ms][1], af[ms][2], af[ms][3],
                            aBase + aRowOff + ms * 2048 + ((g ^ i8) << 4));
            }
            uint32_t bf[8][2];
#pragma unroll
            for (int nsp = 0; nsp < 4; nsp++) {   // each x4 covers 2 ns tiles
                const int g = 2 * kq + b_gsel;
                ldmatrix_x4(bf[2 * nsp][0], bf[2 * nsp][1],
                            bf[2 * nsp + 1][0], bf[2 * nsp + 1][1],
                            bBase + bRowOff + nsp * 2048 + ((g ^ i8) << 4));
            }
#pragma unroll
            for (int ms = 0; ms < 4; ms++)
#pragma unroll
                for (int ns = 0; ns < 8; ns++)
                    mma_f16(acc[ms][ns], af[ms], bf[ns], acc[ms][ns]);
        }
    }

    // epilogue: c0,c1 at (row, 2*lc), c2,c3 at (row+8, 2*lc)
#pragma unroll
    for (int ms = 0; ms < 4; ms++) {
        const int rg = m0 + wm * 64 + ms * 16 + lr;
        float* o0 = out + (size_t)rg * NDIM;
        float* o1 = out + (size_t)(rg + 8) * NDIM;
#pragma unroll
        for (int ns = 0; ns < 8; ns++) {
            const int cg = n0 + wn * 64 + ns * 8 + 2 * lc;
            const float2 bv = *reinterpret_cast<const float2*>(bias + cg);
            float2 v0, v1;
            v0.x = acc[ms][ns][0] + bv.x;  v0.y = acc[ms][ns][1] + bv.y;
            v1.x = acc[ms][ns][2] + bv.x;  v1.y = acc[ms][ns][3] + bv.y;
            *reinterpret_cast<float2*>(o0 + cg) = v0;
            *reinterpret_cast<float2*>(o1 + cg) = v1;
        }
    }
}

// ---------------------------------------------------------------------------
extern "C" void kernel_launch(void* const* d_in, const int* in_sizes, int n_in,
                              void* d_out, int out_size) {
    const float* x = (const float*)d_in[0];      // [4,2048,4096]
    const float* w = (const float*)d_in[1];      // [4096,4096]
    const float* bias = (const float*)d_in[2];   // [4096]
    const float* kk = (const float*)d_in[3];
    const float* aa = (const float*)d_in[4];
    float* out = (float*)d_out;                  // [4,2048,4096]

    prep_w<<<NDIM * KDIM / 2048, 256>>>((const float4*)w, kk, aa);
    prep_x<<<MDIM * KDIM / 2048, 256>>>((const float4*)x);

    cudaFuncSetAttribute(gemm_kernel, cudaFuncAttributeMaxDynamicSharedMemorySize, SMEM_BYTES);
    gemm_kernel<<<(MDIM / TM) * (NDIM / TN), 128, SMEM_BYTES>>>(bias, out);
}

// round 9
// speedup vs baseline: 2.6019x; 1.0701x over previous
#include <cuda_runtime.h>
#include <cuda_fp16.h>
#include <cstdint>
#include <math.h>

// ============================================================================
// BinaryLinear: y[8192,4096] = x[8192,4096] @ (aa*tanh(kk*W))^T + bias
// fp16 mma.sync.m16n8k16 register GEMM (fp32 accumulate), ldmatrix.x4 frags,
// double-buffered fragments (LDS latency hidden under HMMA).
// CTA 128x128, 4 warps (2x2), warp tile 64x64, 3-stage cp.async, TK=64 halves.
// 2 CTAs/SM; SW128 swizzle (128B rows). Single fused prep kernel.
// ============================================================================

#define MDIM 8192
#define NDIM 4096
#define KDIM 4096

#define TM 128
#define TN 128
#define TK 64                          // halves per stage-row (128B)
#define NSTAGES 3
#define KITERS (KDIM / TK)             // 64

#define A_STAGE_BYTES (TM * TK * 2)    // 16384
#define B_STAGE_BYTES (TN * TK * 2)    // 16384
#define STAGE_BYTES (A_STAGE_BYTES + B_STAGE_BYTES)     // 32768
#define SMEM_BYTES (NSTAGES * STAGE_BYTES)              // 98304

#define W_PREP_BLOCKS (NDIM * KDIM / 2048)   // 8192
#define X_PREP_BLOCKS (MDIM * KDIM / 2048)   // 16384

// fp16 operands (persistent scratch)
__device__ __half g_wh[NDIM * KDIM];   // fp16(aa*tanh(kk*W))
__device__ __half g_xh[MDIM * KDIM];   // fp16(x)

// ---------------------------------------------------------------------------
__device__ __forceinline__ uint32_t smem_u32(const void* p) {
    uint32_t a;
    asm("{ .reg .u64 t; cvta.to.shared.u64 t, %1; cvt.u32.u64 %0, t; }" : "=r"(a) : "l"(p));
    return a;
}

__device__ __forceinline__ void cp_async16(uint32_t smem_dst, const void* gmem_src) {
    asm volatile("cp.async.cg.shared.global [%0], [%1], 16;" :: "r"(smem_dst), "l"(gmem_src));
}
#define CP_COMMIT() asm volatile("cp.async.commit_group;" ::: "memory")
#define CP_WAIT(n)  asm volatile("cp.async.wait_group %0;" :: "n"(n) : "memory")

__device__ __forceinline__ void ldmatrix_x4(uint32_t& r0, uint32_t& r1,
                                            uint32_t& r2, uint32_t& r3, uint32_t addr) {
    asm volatile("ldmatrix.sync.aligned.m8n8.x4.shared.b16 {%0,%1,%2,%3}, [%4];"
                 : "=r"(r0), "=r"(r1), "=r"(r2), "=r"(r3) : "r"(addr));
}

__device__ __forceinline__ void mma_f16(float d[4], const uint32_t a[4],
                                        const uint32_t b[2], const float c[4]) {
    asm volatile(
        "mma.sync.aligned.m16n8k16.row.col.f32.f16.f16.f32 "
        "{%0,%1,%2,%3}, {%4,%5,%6,%7}, {%8,%9}, {%10,%11,%12,%13};"
        : "=f"(d[0]), "=f"(d[1]), "=f"(d[2]), "=f"(d[3])
        : "r"(a[0]), "r"(a[1]), "r"(a[2]), "r"(a[3]),
          "r"(b[0]), "r"(b[1]),
          "f"(c[0]), "f"(c[1]), "f"(c[2]), "f"(c[3]));
}

// ---------------------------------------------------------------------------
// Fused prep: blocks [0, W_PREP_BLOCKS) convert W (with tanh), the rest X.
// 8 floats -> 8 halves per thread (16B store).
// ---------------------------------------------------------------------------
__global__ void __launch_bounds__(256) prep_all(const float4* __restrict__ w,
                                                const float4* __restrict__ x,
                                                const float* __restrict__ kk,
                                                const float* __restrict__ aa) {
    if (blockIdx.x < W_PREP_BLOCKS) {
        int i = blockIdx.x * 256 + threadIdx.x;
        float k = *kk, a = *aa;
        float4 v0 = w[2 * i], v1 = w[2 * i + 1];
        __half2 h0 = __floats2half2_rn(a * tanhf(k * v0.x), a * tanhf(k * v0.y));
        __half2 h1 = __floats2half2_rn(a * tanhf(k * v0.z), a * tanhf(k * v0.w));
        __half2 h2 = __floats2half2_rn(a * tanhf(k * v1.x), a * tanhf(k * v1.y));
        __half2 h3 = __floats2half2_rn(a * tanhf(k * v1.z), a * tanhf(k * v1.w));
        uint4 o;
        o.x = *reinterpret_cast<uint32_t*>(&h0);
        o.y = *reinterpret_cast<uint32_t*>(&h1);
        o.z = *reinterpret_cast<uint32_t*>(&h2);
        o.w = *reinterpret_cast<uint32_t*>(&h3);
        reinterpret_cast<uint4*>(g_wh)[i] = o;
    } else {
        int i = (blockIdx.x - W_PREP_BLOCKS) * 256 + threadIdx.x;
        float4 v0 = x[2 * i], v1 = x[2 * i + 1];
        __half2 h0 = __floats2half2_rn(v0.x, v0.y);
        __half2 h1 = __floats2half2_rn(v0.z, v0.w);
        __half2 h2 = __floats2half2_rn(v1.x, v1.y);
        __half2 h3 = __floats2half2_rn(v1.z, v1.w);
        uint4 o;
        o.x = *reinterpret_cast<uint32_t*>(&h0);
        o.y = *reinterpret_cast<uint32_t*>(&h1);
        o.z = *reinterpret_cast<uint32_t*>(&h2);
        o.w = *reinterpret_cast<uint32_t*>(&h3);
        reinterpret_cast<uint4*>(g_xh)[i] = o;
    }
}

// ---------------------------------------------------------------------------
// SMEM: rows of 64 halves (128B = 8 x 16B granules), SW128 swizzle:
// granule c of row r stored at slot (c ^ (r&7)).
// Load one 64-K stage: A 128x64h + B 128x64h. 2048 granules / 128 thr = 16 ea.
// ---------------------------------------------------------------------------
__device__ __forceinline__ void load_stage(const __half* __restrict__ xh,
                                           const __half* __restrict__ wh,
                                           int m0, int n0, int k0,
                                           uint32_t sdst, int tid) {
#pragma unroll
    for (int i = 0; i < 8; i++) {                 // A: 1024 granules
        int g = tid + i * 128;
        int row = g >> 3, c = g & 7;
        cp_async16(sdst + row * 128 + ((c ^ (row & 7)) << 4),
                   xh + (size_t)(m0 + row) * KDIM + k0 + c * 8);
    }
#pragma unroll
    for (int i = 0; i < 8; i++) {                 // B: 1024 granules
        int g = tid + i * 128;
        int row = g >> 3, c = g & 7;
        cp_async16(sdst + A_STAGE_BYTES + row * 128 + ((c ^ (row & 7)) << 4),
                   wh + (size_t)(n0 + row) * KDIM + k0 + c * 8);
    }
}

// ---------------------------------------------------------------------------
// GEMM: 4 warps (2x2), warp tile 64x64 (4 x 8 of m16n8k16), 4 k16-steps/stage,
// fragment double-buffer across k16 steps.
// ---------------------------------------------------------------------------
__global__ void __launch_bounds__(128, 2) gemm_kernel(const float* __restrict__ bias,
                                                      float* __restrict__ out) {
    extern __shared__ char smem_raw[];
    const uint32_t sbase = smem_u32(smem_raw);

    const int tid = threadIdx.x;
    const int wid = tid >> 5;
    const int lane = tid & 31;
    const int wm = wid >> 1;          // 0..1 -> 64-row slab
    const int wn = wid & 1;           // 0..1 -> 64-col slab
    const int lr = lane >> 2;         // 0..7
    const int lc = lane & 3;          // 0..3

    // ldmatrix lane decomposition
    const int i8 = lane & 7;          // row within 8x8 matrix
    const int sel = lane >> 3;        // which matrix (0..3)
    const int a_msel = (sel & 1) << 3;
    const int a_gsel = sel >> 1;
    const int b_nsel = (sel >> 1) << 3;
    const int b_gsel = sel & 1;

    const uint32_t aRowOff = (uint32_t)(wm * 64 + a_msel + i8) * 128;
    const uint32_t bRowOff = (uint32_t)(wn * 64 + b_nsel + i8) * 128;

    // grouped tile swizzle: 64 m-tiles x 32 n-tiles, GROUP_M = 8
    const int pid = blockIdx.x;
    const int group = pid >> 8;                   // / (8*32)
    const int rem = pid & 255;
    const int pm = (group << 3) + (rem & 7);
    const int pn = rem >> 3;
    const int m0 = pm * TM;
    const int n0 = pn * TN;

    float acc[4][8][4];
#pragma unroll
    for (int i = 0; i < 4; i++)
#pragma unroll
        for (int j = 0; j < 8; j++) {
            acc[i][j][0] = 0.f; acc[i][j][1] = 0.f;
            acc[i][j][2] = 0.f; acc[i][j][3] = 0.f;
        }

    // prologue: fill stages 0,1
#pragma unroll
    for (int s = 0; s < NSTAGES - 1; s++) {
        load_stage(g_xh, g_wh, m0, n0, s * TK, sbase + s * STAGE_BYTES, tid);
        CP_COMMIT();
    }

    uint32_t af[2][4][4];
    uint32_t bf[2][8][2];

    for (int it = 0; it < KITERS; ++it) {
        const int s = it % NSTAGES;
        CP_WAIT(1);              // stage `it` resident (one group per iter)
        __syncthreads();

        const uint32_t aBase = sbase + s * STAGE_BYTES;
        const uint32_t bBase = aBase + A_STAGE_BYTES;

        // frag load for kq=0 into buffer 0 (starts immediately post-barrier)
        {
            const int ga = a_gsel, gb = b_gsel;
#pragma unroll
            for (int ms = 0; ms < 4; ms++)
                ldmatrix_x4(af[0][ms][0], af[0][ms][1], af[0][ms][2], af[0][ms][3],
                            aBase + aRowOff + ms * 2048 + ((ga ^ i8) << 4));
#pragma unroll
            for (int nsp = 0; nsp < 4; nsp++)
                ldmatrix_x4(bf[0][2 * nsp][0], bf[0][2 * nsp][1],
                            bf[0][2 * nsp + 1][0], bf[0][2 * nsp + 1][1],
                            bBase + bRowOff + nsp * 2048 + ((gb ^ i8) << 4));
        }

        // issue next-stage gmem prefetch
        const int jt = it + NSTAGES - 1;
        if (jt < KITERS)
            load_stage(g_xh, g_wh, m0, n0, jt * TK,
                       sbase + (jt % NSTAGES) * STAGE_BYTES, tid);
        CP_COMMIT();                              // always commit: CP_WAIT(1) stays valid

#pragma unroll
        for (int kq = 0; kq < 4; kq++) {          // 4 x k16 steps
            const int cur = kq & 1, nxt = cur ^ 1;
            if (kq < 3) {                         // prefetch kq+1 frags
                const int ga = 2 * (kq + 1) + a_gsel;
                const int gb = 2 * (kq + 1) + b_gsel;
#pragma unroll
                for (int ms = 0; ms < 4; ms++)
                    ldmatrix_x4(af[nxt][ms][0], af[nxt][ms][1],
                                af[nxt][ms][2], af[nxt][ms][3],
                                aBase + aRowOff + ms * 2048 + ((ga ^ i8) << 4));
#pragma unroll
                for (int nsp = 0; nsp < 4; nsp++)
                    ldmatrix_x4(bf[nxt][2 * nsp][0], bf[nxt][2 * nsp][1],
                                bf[nxt][2 * nsp + 1][0], bf[nxt][2 * nsp + 1][1],
                                bBase + bRowOff + nsp * 2048 + ((gb ^ i8) << 4));
            }
#pragma unroll
            for (int ms = 0; ms < 4; ms++)
#pragma unroll
                for (int ns = 0; ns < 8; ns++)
                    mma_f16(acc[ms][ns], af[cur][ms], bf[cur][ns], acc[ms][ns]);
        }
    }

    // epilogue: c0,c1 at (row, 2*lc), c2,c3 at (row+8, 2*lc)
#pragma unroll
    for (int ms = 0; ms < 4; ms++) {
        const int rg = m0 + wm * 64 + ms * 16 + lr;
        float* o0 = out + (size_t)rg * NDIM;
        float* o1 = out + (size_t)(rg + 8) * NDIM;
#pragma unroll
        for (int ns = 0; ns < 8; ns++) {
            const int cg = n0 + wn * 64 + ns * 8 + 2 * lc;
            const float2 bv = *reinterpret_cast<const float2*>(bias + cg);
            float2 v0, v1;
            v0.x = acc[ms][ns][0] + bv.x;  v0.y = acc[ms][ns][1] + bv.y;
            v1.x = acc[ms][ns][2] + bv.x;  v1.y = acc[ms][ns][3] + bv.y;
            *reinterpret_cast<float2*>(o0 + cg) = v0;
            *reinterpret_cast<float2*>(o1 + cg) = v1;
        }
    }
}

// ---------------------------------------------------------------------------
extern "C" void kernel_launch(void* const* d_in, const int* in_sizes, int n_in,
                              void* d_out, int out_size) {
    const float* x = (const float*)d_in[0];      // [4,2048,4096]
    const float* w = (const float*)d_in[1];      // [4096,4096]
    const float* bias = (const float*)d_in[2];   // [4096]
    const float* kk = (const float*)d_in[3];
    const float* aa = (const float*)d_in[4];
    float* out = (float*)d_out;                  // [4,2048,4096]

    prep_all<<<W_PREP_BLOCKS + X_PREP_BLOCKS, 256>>>((const float4*)w,
                                                     (const float4*)x, kk, aa);

    cudaFuncSetAttribute(gemm_kernel, cudaFuncAttributeMaxDynamicSharedMemorySize, SMEM_BYTES);
    gemm_kernel<<<(MDIM / TM) * (NDIM / TN), 128, SMEM_BYTES>>>(bias, out);
}